// round 13
// baseline (speedup 1.0000x reference)
#include <cuda_runtime.h>
#include <math.h>

#define DM 1024
#define NH 16
#define DH 64
#define B_ 4
#define S_ 2048
#define MTOT (B_*S_)

// Scratch for Q,K,V in [B][H][S][Dh] layout (allowed: __device__ globals).
__device__ float g_q[MTOT * DM];
__device__ float g_k[MTOT * DM];
__device__ float g_v[MTOT * DM];

// ---------------------------------------------------------------------------
// Fused QKV projection: out_z = X @ W_z, scattered to [B][H][S][Dh].
// 128x128 tile, BK=8, 256 threads, 8x8 per thread. Double-buffered smem:
// one __syncthreads per k-step; gmem prefetch overlapped with compute.
// __launch_bounds__(256,2): cap regs at 128 so 2 CTAs/SM are guaranteed.
// z = blockIdx.z selects Q/K/V.
// ---------------------------------------------------------------------------
__global__ __launch_bounds__(256, 2) void qkv_gemm_kernel(
    const float* __restrict__ X, const float* __restrict__ Wq,
    const float* __restrict__ Wk, const float* __restrict__ Wv)
{
    __shared__ __align__(16) float As[2][8][128];
    __shared__ __align__(16) float Bs[2][8][128];

    const int z = blockIdx.z;
    const float* W = (z == 0) ? Wq : ((z == 1) ? Wk : Wv);
    float* dst = (z == 0) ? g_q : ((z == 1) ? g_k : g_v);

    const int m0 = blockIdx.y * 128;
    const int n0 = blockIdx.x * 128;
    const int tid = threadIdx.x;
    const int tx = tid & 15;
    const int ty = tid >> 4;

    // loaders
    const int am = tid >> 1;            // 0..127 (A row)
    const int ah = (tid & 1) << 2;      // 0 or 4 (A k-offset)
    const int bk = tid >> 5;            // 0..7   (B row)
    const int bn = (tid & 31) << 2;     // 0..124 (B col)

    const float* Ap = X + (m0 + am) * DM + ah;
    const float* Bp = W + bk * DM + n0 + bn;

    float acc[8][8];
#pragma unroll
    for (int i = 0; i < 8; i++)
#pragma unroll
        for (int j = 0; j < 8; j++) acc[i][j] = 0.0f;

    // prologue: fill buffer 0
    {
        float4 av = *(const float4*)(Ap);
        float4 bv = *(const float4*)(Bp);
        As[0][ah + 0][am] = av.x;
        As[0][ah + 1][am] = av.y;
        As[0][ah + 2][am] = av.z;
        As[0][ah + 3][am] = av.w;
        *(float4*)&Bs[0][bk][bn] = bv;
    }
    __syncthreads();

    int p = 0;
    for (int k0 = 8; k0 <= DM; k0 += 8) {
        float4 av, bv;
        const bool more = (k0 < DM);
        if (more) {
            av = *(const float4*)(Ap + k0);
            bv = *(const float4*)(Bp + k0 * DM);
        }
        // compute from buffer p
#pragma unroll
        for (int kk = 0; kk < 8; kk++) {
            float4 a0 = *(const float4*)&As[p][kk][4 * ty];
            float4 a1 = *(const float4*)&As[p][kk][64 + 4 * ty];
            float4 b0 = *(const float4*)&Bs[p][kk][4 * tx];
            float4 b1 = *(const float4*)&Bs[p][kk][64 + 4 * tx];
            float a[8] = {a0.x, a0.y, a0.z, a0.w, a1.x, a1.y, a1.z, a1.w};
            float b[8] = {b0.x, b0.y, b0.z, b0.w, b1.x, b1.y, b1.z, b1.w};
#pragma unroll
            for (int i = 0; i < 8; i++)
#pragma unroll
                for (int j = 0; j < 8; j++)
                    acc[i][j] += a[i] * b[j];
        }
        if (more) {
            const int q = p ^ 1;
            As[q][ah + 0][am] = av.x;
            As[q][ah + 1][am] = av.y;
            As[q][ah + 2][am] = av.z;
            As[q][ah + 3][am] = av.w;
            *(float4*)&Bs[q][bk][bn] = bv;
            __syncthreads();   // publishes buf q; also: all compute on p done
            p = q;
        }
    }

    // Epilogue: scatter to [B][H][S][Dh]. n-groups of 4 cols stay in one head.
#pragma unroll
    for (int i = 0; i < 8; i++) {
        const int m = m0 + ((i < 4) ? (4 * ty + i) : (64 + 4 * ty + (i - 4)));
        const int bb = m / S_;
        const int ss = m - bb * S_;
#pragma unroll
        for (int jg = 0; jg < 2; jg++) {
            const int n = n0 + ((jg == 0) ? (4 * tx) : (64 + 4 * tx));
            const int h = n >> 6;
            const int d = n & 63;
            float4 v;
            v.x = acc[i][jg * 4 + 0];
            v.y = acc[i][jg * 4 + 1];
            v.z = acc[i][jg * 4 + 2];
            v.w = acc[i][jg * 4 + 3];
            *(float4*)&dst[((bb * NH + h) * S_ + ss) * DH + d] = v;
        }
    }
}

// ---------------------------------------------------------------------------
// Flash attention, fp32, causal mask k <= q+1 (tril diagonal=1).
// Block = (qtile 64, head, batch), 256 threads (16x16).
// qt REVERSED vs blockIdx.x (LPT: heaviest CTAs first).
// 1/sqrt(64) folded into the Q smem load (scores come out pre-scaled).
// Interior k-tiles (jt < qt) are provably unmasked -> mask ops skipped.
// P OVERLAYS the K smem region (KPs): static smem stays at 48KB.
// Inner hot loops unrolled x8 (halves loop-branch overhead vs x4; body
// stays within I$ budget).
// __launch_bounds__(256,2): 2 CTAs/SM (48KB smem/CTA, regs capped at 128).
// Thread (ty,tx): owns q rows {4ty..4ty+3}; S-phase cols k {4tx..4tx+3};
// PV-phase cols d {4tx..4tx+3}. P written [q][k] row-major so PV reads of P
// are warp-broadcast.
// ---------------------------------------------------------------------------
__global__ __launch_bounds__(256, 2) void attn_kernel(float* __restrict__ out)
{
    __shared__ __align__(16) float Qs[64 * 64];   // Qs[d*64 + q], pre-scaled
    __shared__ __align__(16) float KPs[64 * 64];  // K: [d*64+k]; then P: [q*64+k]
    __shared__ __align__(16) float Vs[64 * 64];   // Vs[k*64 + d]

    const int qt = (S_ / 64 - 1) - blockIdx.x;    // LPT: big qt first
    const int h  = blockIdx.y;
    const int b  = blockIdx.z;
    const int q0 = qt * 64;
    const int tid = threadIdx.x;
    const int tx = tid & 15;
    const int ty = tid >> 4;

    const float* Qg = g_q + (b * NH + h) * S_ * DH;
    const float* Kg = g_k + (b * NH + h) * S_ * DH;
    const float* Vg = g_v + (b * NH + h) * S_ * DH;

    // Load Q tile transposed: Qs[d][q], folding in the 1/sqrt(Dh) scale.
    {
        const int qq = tid >> 2;       // 0..63
        const int dc = tid & 3;        // 0..3
#pragma unroll
        for (int it = 0; it < 4; it++) {
            const int d4 = 4 * (dc + 4 * it);   // 0..60
            float4 v = *(const float4*)(Qg + (q0 + qq) * DH + d4);
            Qs[(d4 + 0) * 64 + qq] = v.x * 0.125f;
            Qs[(d4 + 1) * 64 + qq] = v.y * 0.125f;
            Qs[(d4 + 2) * 64 + qq] = v.z * 0.125f;
            Qs[(d4 + 3) * 64 + qq] = v.w * 0.125f;
        }
    }

    float m_run[4], l_run[4], O[4][4];
#pragma unroll
    for (int i = 0; i < 4; i++) {
        m_run[i] = -INFINITY;
        l_run[i] = 0.0f;
#pragma unroll
        for (int j = 0; j < 4; j++) O[i][j] = 0.0f;
    }

    const int nt = min(qt + 2, S_ / 64);  // causal: last needed k-tile index = qt+1

    for (int jt = 0; jt < nt; jt++) {
        __syncthreads();  // prior-iter consumers done (also publishes Qs on iter 0)

        // Load K tile transposed KPs[d][k], V tile natural Vs[k][d]
        {
            const int kk = tid >> 2;
            const int dc = tid & 3;
#pragma unroll
            for (int it = 0; it < 4; it++) {
                const int d4 = 4 * (dc + 4 * it);
                float4 v = *(const float4*)(Kg + (jt * 64 + kk) * DH + d4);
                KPs[(d4 + 0) * 64 + kk] = v.x;
                KPs[(d4 + 1) * 64 + kk] = v.y;
                KPs[(d4 + 2) * 64 + kk] = v.z;
                KPs[(d4 + 3) * 64 + kk] = v.w;
            }
            const int dc2 = tid & 15;
            const int kr = tid >> 4;
#pragma unroll
            for (int it = 0; it < 4; it++) {
                const int k = kr + 16 * it;
                float4 v = *(const float4*)(Vg + (jt * 64 + k) * DH + 4 * dc2);
                *(float4*)&Vs[k * 64 + 4 * dc2] = v;
            }
        }
        __syncthreads();   // publish K/V

        // S = (Q/8) K^T  (reduce over d) -- already scaled via Qs
        float s[4][4];
#pragma unroll
        for (int i = 0; i < 4; i++)
#pragma unroll
            for (int j = 0; j < 4; j++) s[i][j] = 0.0f;

#pragma unroll 8
        for (int d = 0; d < 64; d++) {
            float4 qv = *(const float4*)&Qs[d * 64 + 4 * ty];
            float4 kv = *(const float4*)&KPs[d * 64 + 4 * tx];
            float qa[4] = {qv.x, qv.y, qv.z, qv.w};
            float ka[4] = {kv.x, kv.y, kv.z, kv.w};
#pragma unroll
            for (int i = 0; i < 4; i++)
#pragma unroll
                for (int j = 0; j < 4; j++)
                    s[i][j] += qa[i] * ka[j];
        }

        // causal mask (k <= q+1 allowed) only on boundary tiles.
        // For jt < qt: k <= jt*64+63 <= q0-1 < q+1 for all rows -> unmasked.
        if (jt >= qt) {
            const int gqb = q0 + 4 * ty;
            const int gkb = jt * 64 + 4 * tx;
#pragma unroll
            for (int i = 0; i < 4; i++)
#pragma unroll
                for (int j = 0; j < 4; j++)
                    if (gkb + j > gqb + i + 1) s[i][j] = -INFINITY;
        }

        // online softmax (row reduce across the 16 tx-lanes of each q-row)
        float p[4][4];
#pragma unroll
        for (int i = 0; i < 4; i++) {
            float mx = fmaxf(fmaxf(s[i][0], s[i][1]), fmaxf(s[i][2], s[i][3]));
            mx = fmaxf(mx, __shfl_xor_sync(0xffffffffu, mx, 1));
            mx = fmaxf(mx, __shfl_xor_sync(0xffffffffu, mx, 2));
            mx = fmaxf(mx, __shfl_xor_sync(0xffffffffu, mx, 4));
            mx = fmaxf(mx, __shfl_xor_sync(0xffffffffu, mx, 8));
            const float m_new = fmaxf(m_run[i], mx);
            const float a = __expf(m_run[i] - m_new);  // 0 on first tile
            float rs = 0.0f;
#pragma unroll
            for (int j = 0; j < 4; j++) {
                p[i][j] = __expf(s[i][j] - m_new);  // -inf -> 0
                rs += p[i][j];
            }
            rs += __shfl_xor_sync(0xffffffffu, rs, 1);
            rs += __shfl_xor_sync(0xffffffffu, rs, 2);
            rs += __shfl_xor_sync(0xffffffffu, rs, 4);
            rs += __shfl_xor_sync(0xffffffffu, rs, 8);
            l_run[i] = l_run[i] * a + rs;
            m_run[i] = m_new;
#pragma unroll
            for (int j = 0; j < 4; j++) O[i][j] *= a;
        }

        __syncthreads();  // all K reads complete before overlaying P

        // write P row-major [q][k] into the K smem region
#pragma unroll
        for (int i = 0; i < 4; i++) {
            float4 v;
            v.x = p[i][0]; v.y = p[i][1]; v.z = p[i][2]; v.w = p[i][3];
            *(float4*)&KPs[(4 * ty + i) * 64 + 4 * tx] = v;
        }
        __syncthreads();   // publish P

        // O += P @ V  (reduce over k; P reads are warp-broadcast)
#pragma unroll 8
        for (int k = 0; k < 64; k++) {
            float pv[4];
#pragma unroll
            for (int i = 0; i < 4; i++) pv[i] = KPs[(4 * ty + i) * 64 + k];
            float4 vvv = *(const float4*)&Vs[k * 64 + 4 * tx];
            float vv[4] = {vvv.x, vvv.y, vvv.z, vvv.w};
#pragma unroll
            for (int i = 0; i < 4; i++)
#pragma unroll
                for (int j = 0; j < 4; j++)
                    O[i][j] += pv[i] * vv[j];
        }
    }

    // epilogue: out[b][s][h*64+d] = O / l
#pragma unroll
    for (int i = 0; i < 4; i++) {
        const float inv = 1.0f / l_run[i];
        const int q = q0 + 4 * ty + i;
        float4 v;
        v.x = O[i][0] * inv;
        v.y = O[i][1] * inv;
        v.z = O[i][2] * inv;
        v.w = O[i][3] * inv;
        *(float4*)&out[(b * S_ + q) * DM + h * DH + 4 * tx] = v;
    }
}

extern "C" void kernel_launch(void* const* d_in, const int* in_sizes, int n_in,
                              void* d_out, int out_size)
{
    const float* X  = (const float*)d_in[0];
    const float* Wq = (const float*)d_in[1];
    const float* Wk = (const float*)d_in[2];
    const float* Wv = (const float*)d_in[3];
    float* out = (float*)d_out;

    dim3 gg(DM / 128, MTOT / 128, 3);
    qkv_gemm_kernel<<<gg, 256>>>(X, Wq, Wk, Wv);

    dim3 ga(S_ / 64, NH, B_);
    attn_kernel<<<ga, 256>>>(out);
}

// round 15
// speedup vs baseline: 1.0067x; 1.0067x over previous
#include <cuda_runtime.h>
#include <math.h>

#define DM 1024
#define NH 16
#define DH 64
#define B_ 4
#define S_ 2048
#define MTOT (B_*S_)

// Scratch for Q,K,V in [B][H][S][Dh] layout (allowed: __device__ globals).
__device__ float g_q[MTOT * DM];
__device__ float g_k[MTOT * DM];
__device__ float g_v[MTOT * DM];

// ---------------------------------------------------------------------------
// Fused QKV projection: out_z = X @ W_z, scattered to [B][H][S][Dh].
// 128x128 tile, BK=8, 256 threads, 8x8 per thread. Double-buffered smem.
// Measured (R13): whole-op 2084us total, GEMM ~983us (~52 TF/s, ~76% of the
// recalibrated 128 MAC/cyc/SM fp32 roofline). Unchanged pending attn result.
// ---------------------------------------------------------------------------
__global__ __launch_bounds__(256, 2) void qkv_gemm_kernel(
    const float* __restrict__ X, const float* __restrict__ Wq,
    const float* __restrict__ Wk, const float* __restrict__ Wv)
{
    __shared__ __align__(16) float As[2][8][128];
    __shared__ __align__(16) float Bs[2][8][128];

    const int z = blockIdx.z;
    const float* W = (z == 0) ? Wq : ((z == 1) ? Wk : Wv);
    float* dst = (z == 0) ? g_q : ((z == 1) ? g_k : g_v);

    const int m0 = blockIdx.y * 128;
    const int n0 = blockIdx.x * 128;
    const int tid = threadIdx.x;
    const int tx = tid & 15;
    const int ty = tid >> 4;

    // loaders
    const int am = tid >> 1;            // 0..127 (A row)
    const int ah = (tid & 1) << 2;      // 0 or 4 (A k-offset)
    const int bk = tid >> 5;            // 0..7   (B row)
    const int bn = (tid & 31) << 2;     // 0..124 (B col)

    const float* Ap = X + (m0 + am) * DM + ah;
    const float* Bp = W + bk * DM + n0 + bn;

    float acc[8][8];
#pragma unroll
    for (int i = 0; i < 8; i++)
#pragma unroll
        for (int j = 0; j < 8; j++) acc[i][j] = 0.0f;

    // prologue: fill buffer 0
    {
        float4 av = *(const float4*)(Ap);
        float4 bv = *(const float4*)(Bp);
        As[0][ah + 0][am] = av.x;
        As[0][ah + 1][am] = av.y;
        As[0][ah + 2][am] = av.z;
        As[0][ah + 3][am] = av.w;
        *(float4*)&Bs[0][bk][bn] = bv;
    }
    __syncthreads();

    int p = 0;
    for (int k0 = 8; k0 <= DM; k0 += 8) {
        float4 av, bv;
        const bool more = (k0 < DM);
        if (more) {
            av = *(const float4*)(Ap + k0);
            bv = *(const float4*)(Bp + k0 * DM);
        }
        // compute from buffer p
#pragma unroll
        for (int kk = 0; kk < 8; kk++) {
            float4 a0 = *(const float4*)&As[p][kk][4 * ty];
            float4 a1 = *(const float4*)&As[p][kk][64 + 4 * ty];
            float4 b0 = *(const float4*)&Bs[p][kk][4 * tx];
            float4 b1 = *(const float4*)&Bs[p][kk][64 + 4 * tx];
            float a[8] = {a0.x, a0.y, a0.z, a0.w, a1.x, a1.y, a1.z, a1.w};
            float b[8] = {b0.x, b0.y, b0.z, b0.w, b1.x, b1.y, b1.z, b1.w};
#pragma unroll
            for (int i = 0; i < 8; i++)
#pragma unroll
                for (int j = 0; j < 8; j++)
                    acc[i][j] += a[i] * b[j];
        }
        if (more) {
            const int q = p ^ 1;
            As[q][ah + 0][am] = av.x;
            As[q][ah + 1][am] = av.y;
            As[q][ah + 2][am] = av.z;
            As[q][ah + 3][am] = av.w;
            *(float4*)&Bs[q][bk][bn] = bv;
            __syncthreads();   // publishes buf q; also: all compute on p done
            p = q;
        }
    }

    // Epilogue: scatter to [B][H][S][Dh]. n-groups of 4 cols stay in one head.
#pragma unroll
    for (int i = 0; i < 8; i++) {
        const int m = m0 + ((i < 4) ? (4 * ty + i) : (64 + 4 * ty + (i - 4)));
        const int bb = m / S_;
        const int ss = m - bb * S_;
#pragma unroll
        for (int jg = 0; jg < 2; jg++) {
            const int n = n0 + ((jg == 0) ? (4 * tx) : (64 + 4 * tx));
            const int h = n >> 6;
            const int d = n & 63;
            float4 v;
            v.x = acc[i][jg * 4 + 0];
            v.y = acc[i][jg * 4 + 1];
            v.z = acc[i][jg * 4 + 2];
            v.w = acc[i][jg * 4 + 3];
            *(float4*)&dst[((bb * NH + h) * S_ + ss) * DH + d] = v;
        }
    }
}

// ---------------------------------------------------------------------------
// Flash attention, fp32, causal mask k <= q+1 (tril diagonal=1).
// R13 ncu: L1(smem crossbar)=77.3%, fma=44.5% -> crossbar-bound. Wavefront
// model (validated: predicted fma/L1=0.57, measured 0.576): PV phase spent
// 16 wf per 4-k on scalar P loads. PENDING MEASUREMENT: PV P loads
// vectorized to LDS.128 over k-groups of 4 (broadcast, 1 wf each):
// per-tile wavefronts 576 -> 384, predicted attn 1101 -> ~800-870us.
// Block = (qtile 64, head, batch), 256 threads (16x16). LPT order.
// 1/sqrt(64) folded into Q load. Interior tiles skip mask. P overlays K.
// ---------------------------------------------------------------------------
__global__ __launch_bounds__(256, 2) void attn_kernel(float* __restrict__ out)
{
    __shared__ __align__(16) float Qs[64 * 64];   // Qs[d*64 + q], pre-scaled
    __shared__ __align__(16) float KPs[64 * 64];  // K: [d*64+k]; then P: [q*64+k]
    __shared__ __align__(16) float Vs[64 * 64];   // Vs[k*64 + d]

    const int qt = (S_ / 64 - 1) - blockIdx.x;    // LPT: big qt first
    const int h  = blockIdx.y;
    const int b  = blockIdx.z;
    const int q0 = qt * 64;
    const int tid = threadIdx.x;
    const int tx = tid & 15;
    const int ty = tid >> 4;

    const float* Qg = g_q + (b * NH + h) * S_ * DH;
    const float* Kg = g_k + (b * NH + h) * S_ * DH;
    const float* Vg = g_v + (b * NH + h) * S_ * DH;

    // Load Q tile transposed: Qs[d][q], folding in the 1/sqrt(Dh) scale.
    {
        const int qq = tid >> 2;       // 0..63
        const int dc = tid & 3;        // 0..3
#pragma unroll
        for (int it = 0; it < 4; it++) {
            const int d4 = 4 * (dc + 4 * it);   // 0..60
            float4 v = *(const float4*)(Qg + (q0 + qq) * DH + d4);
            Qs[(d4 + 0) * 64 + qq] = v.x * 0.125f;
            Qs[(d4 + 1) * 64 + qq] = v.y * 0.125f;
            Qs[(d4 + 2) * 64 + qq] = v.z * 0.125f;
            Qs[(d4 + 3) * 64 + qq] = v.w * 0.125f;
        }
    }

    float m_run[4], l_run[4], O[4][4];
#pragma unroll
    for (int i = 0; i < 4; i++) {
        m_run[i] = -INFINITY;
        l_run[i] = 0.0f;
#pragma unroll
        for (int j = 0; j < 4; j++) O[i][j] = 0.0f;
    }

    const int nt = min(qt + 2, S_ / 64);  // causal: last needed k-tile index = qt+1

    for (int jt = 0; jt < nt; jt++) {
        __syncthreads();  // prior-iter consumers done (also publishes Qs on iter 0)

        // Load K tile transposed KPs[d][k], V tile natural Vs[k][d]
        {
            const int kk = tid >> 2;
            const int dc = tid & 3;
#pragma unroll
            for (int it = 0; it < 4; it++) {
                const int d4 = 4 * (dc + 4 * it);
                float4 v = *(const float4*)(Kg + (jt * 64 + kk) * DH + d4);
                KPs[(d4 + 0) * 64 + kk] = v.x;
                KPs[(d4 + 1) * 64 + kk] = v.y;
                KPs[(d4 + 2) * 64 + kk] = v.z;
                KPs[(d4 + 3) * 64 + kk] = v.w;
            }
            const int dc2 = tid & 15;
            const int kr = tid >> 4;
#pragma unroll
            for (int it = 0; it < 4; it++) {
                const int k = kr + 16 * it;
                float4 v = *(const float4*)(Vg + (jt * 64 + k) * DH + 4 * dc2);
                *(float4*)&Vs[k * 64 + 4 * dc2] = v;
            }
        }
        __syncthreads();   // publish K/V

        // S = (Q/8) K^T  (reduce over d) -- already scaled via Qs
        float s[4][4];
#pragma unroll
        for (int i = 0; i < 4; i++)
#pragma unroll
            for (int j = 0; j < 4; j++) s[i][j] = 0.0f;

#pragma unroll 8
        for (int d = 0; d < 64; d++) {
            float4 qv = *(const float4*)&Qs[d * 64 + 4 * ty];
            float4 kv = *(const float4*)&KPs[d * 64 + 4 * tx];
            float qa[4] = {qv.x, qv.y, qv.z, qv.w};
            float ka[4] = {kv.x, kv.y, kv.z, kv.w};
#pragma unroll
            for (int i = 0; i < 4; i++)
#pragma unroll
                for (int j = 0; j < 4; j++)
                    s[i][j] += qa[i] * ka[j];
        }

        // causal mask (k <= q+1 allowed) only on boundary tiles.
        // For jt < qt: k <= jt*64+63 <= q0-1 < q+1 for all rows -> unmasked.
        if (jt >= qt) {
            const int gqb = q0 + 4 * ty;
            const int gkb = jt * 64 + 4 * tx;
#pragma unroll
            for (int i = 0; i < 4; i++)
#pragma unroll
                for (int j = 0; j < 4; j++)
                    if (gkb + j > gqb + i + 1) s[i][j] = -INFINITY;
        }

        // online softmax (row reduce across the 16 tx-lanes of each q-row)
        float p[4][4];
#pragma unroll
        for (int i = 0; i < 4; i++) {
            float mx = fmaxf(fmaxf(s[i][0], s[i][1]), fmaxf(s[i][2], s[i][3]));
            mx = fmaxf(mx, __shfl_xor_sync(0xffffffffu, mx, 1));
            mx = fmaxf(mx, __shfl_xor_sync(0xffffffffu, mx, 2));
            mx = fmaxf(mx, __shfl_xor_sync(0xffffffffu, mx, 4));
            mx = fmaxf(mx, __shfl_xor_sync(0xffffffffu, mx, 8));
            const float m_new = fmaxf(m_run[i], mx);
            const float a = __expf(m_run[i] - m_new);  // 0 on first tile
            float rs = 0.0f;
#pragma unroll
            for (int j = 0; j < 4; j++) {
                p[i][j] = __expf(s[i][j] - m_new);  // -inf -> 0
                rs += p[i][j];
            }
            rs += __shfl_xor_sync(0xffffffffu, rs, 1);
            rs += __shfl_xor_sync(0xffffffffu, rs, 2);
            rs += __shfl_xor_sync(0xffffffffu, rs, 4);
            rs += __shfl_xor_sync(0xffffffffu, rs, 8);
            l_run[i] = l_run[i] * a + rs;
            m_run[i] = m_new;
#pragma unroll
            for (int j = 0; j < 4; j++) O[i][j] *= a;
        }

        __syncthreads();  // all K reads complete before overlaying P

        // write P row-major [q][k] into the K smem region
#pragma unroll
        for (int i = 0; i < 4; i++) {
            float4 v;
            v.x = p[i][0]; v.y = p[i][1]; v.z = p[i][2]; v.w = p[i][3];
            *(float4*)&KPs[(4 * ty + i) * 64 + 4 * tx] = v;
        }
        __syncthreads();   // publish P

        // O += P @ V, k grouped by 4. P loaded as LDS.128 (broadcast, 1 wf)
        // instead of 16x LDS.32 (16 wf) -> PV crossbar work halves.
#pragma unroll 4
        for (int kg = 0; kg < 16; kg++) {
            float pr[4][4];
#pragma unroll
            for (int i = 0; i < 4; i++) {
                float4 pq = *(const float4*)&KPs[(4 * ty + i) * 64 + 4 * kg];
                pr[i][0] = pq.x; pr[i][1] = pq.y; pr[i][2] = pq.z; pr[i][3] = pq.w;
            }
#pragma unroll
            for (int jj = 0; jj < 4; jj++) {
                const int k = 4 * kg + jj;
                float4 vvv = *(const float4*)&Vs[k * 64 + 4 * tx];
                float vv[4] = {vvv.x, vvv.y, vvv.z, vvv.w};
#pragma unroll
                for (int i = 0; i < 4; i++)
#pragma unroll
                    for (int j = 0; j < 4; j++)
                        O[i][j] += pr[i][jj] * vv[j];
            }
        }
    }

    // epilogue: out[b][s][h*64+d] = O / l
#pragma unroll
    for (int i = 0; i < 4; i++) {
        const float inv = 1.0f / l_run[i];
        const int q = q0 + 4 * ty + i;
        float4 v;
        v.x = O[i][0] * inv;
        v.y = O[i][1] * inv;
        v.z = O[i][2] * inv;
        v.w = O[i][3] * inv;
        *(float4*)&out[(b * S_ + q) * DM + h * DH + 4 * tx] = v;
    }
}

extern "C" void kernel_launch(void* const* d_in, const int* in_sizes, int n_in,
                              void* d_out, int out_size)
{
    const float* X  = (const float*)d_in[0];
    const float* Wq = (const float*)d_in[1];
    const float* Wk = (const float*)d_in[2];
    const float* Wv = (const float*)d_in[3];
    float* out = (float*)d_out;

    dim3 gg(DM / 128, MTOT / 128, 3);
    qkv_gemm_kernel<<<gg, 256>>>(X, Wq, Wk, Wv);

    dim3 ga(S_ / 64, NH, B_);
    attn_kernel<<<ga, 256>>>(out);
}